// round 15
// baseline (speedup 1.0000x reference)
#include <cuda_runtime.h>
#include <cuda_fp16.h>
#include <cstdint>

#define HWD 256
#define NTILES 8192      // 8 batches * 32 * 32 tiles of 8x8 pixels

// ---------------- device scratch ----------------
__device__ float g_xbuf[(size_t)8 * HWD * HWD * 48];

// ---------------- threefry2x32 (exact JAX, 20 rounds) ----------------
__host__ __device__ __forceinline__ void threefry2x32(
    uint32_t k0, uint32_t k1, uint32_t x0, uint32_t x1, uint32_t& o0, uint32_t& o1) {
  uint32_t ks2 = k0 ^ k1 ^ 0x1BD11BDAu;
  uint32_t v0 = x0 + k0, v1 = x1 + k1;
#define TF_ROTL(v, r) (((v) << (r)) | ((v) >> (32 - (r))))
#define TF_RND(r) { v0 += v1; v1 = TF_ROTL(v1, r); v1 ^= v0; }
  TF_RND(13) TF_RND(15) TF_RND(26) TF_RND(6)
  v0 += k1;  v1 += ks2 + 1u;
  TF_RND(17) TF_RND(29) TF_RND(16) TF_RND(24)
  v0 += ks2; v1 += k0 + 2u;
  TF_RND(13) TF_RND(15) TF_RND(26) TF_RND(6)
  v0 += k0;  v1 += k1 + 3u;
  TF_RND(17) TF_RND(29) TF_RND(16) TF_RND(24)
  v0 += k1;  v1 += ks2 + 4u;
  TF_RND(13) TF_RND(15) TF_RND(26) TF_RND(6)
  v0 += ks2; v1 += k0 + 5u;
#undef TF_RND
#undef TF_ROTL
  o0 = v0; o1 = v1;
}

// ---------------- helpers ----------------
__device__ __forceinline__ void mma_f16(float* c, uint32_t a0, uint32_t a1,
                                        uint32_t a2, uint32_t a3,
                                        uint32_t b0, uint32_t b1) {
  asm volatile(
    "mma.sync.aligned.m16n8k16.row.col.f32.f16.f16.f32 "
    "{%0,%1,%2,%3},{%4,%5,%6,%7},{%8,%9},{%0,%1,%2,%3};"
    : "+f"(c[0]), "+f"(c[1]), "+f"(c[2]), "+f"(c[3])
    : "r"(a0), "r"(a1), "r"(a2), "r"(a3), "r"(b0), "r"(b1));
}
#define LDMATRIX_X4(r0, r1, r2, r3, addr) \
  asm volatile("ldmatrix.sync.aligned.m8n8.x4.shared.b16 {%0,%1,%2,%3},[%4];" \
    : "=r"(r0), "=r"(r1), "=r"(r2), "=r"(r3) : "r"(addr))
#define LDS_V4(r0, r1, r2, r3, addr) \
  asm volatile("ld.shared.v4.u32 {%0,%1,%2,%3},[%4];" \
    : "=r"(r0), "=r"(r1), "=r"(r2), "=r"(r3) : "r"(addr))
#define LDS_V2(r0, r1, addr) \
  asm volatile("ld.shared.v2.u32 {%0,%1},[%2];" \
    : "=r"(r0), "=r"(r1) : "r"(addr))
#define CP_ASYNC16(dst, src) \
  asm volatile("cp.async.ca.shared.global [%0], [%1], 16;" :: "r"(dst), "l"(src))
#define CP_COMMIT() asm volatile("cp.async.commit_group;" ::: "memory")
#define CP_WAIT0()  asm volatile("cp.async.wait_group 0;" ::: "memory")

__device__ __forceinline__ uint32_t smem_u32_of(const void* p) {
  uint32_t a;
  asm("{ .reg .u64 t; cvta.to.shared.u64 t, %1; cvt.u32.u64 %0, t; }" : "=r"(a) : "l"(p));
  return a;
}
__device__ __forceinline__ uint32_t packh2(float a, float b) {
  __half2 h = __floats2half2_rn(a, b);
  return *(uint32_t*)&h;
}

// ---------------- shared memory layout (float offsets) ----------------
#define F_FIRE  8             // 64
#define F_B1    72            // 256
#define F_FILT  328           // 864
#define F_HALO  1192          // 2 x 4880 = 9760 (double-buffered staging)
#define F_PH    10952         // P half[64][152] = 4864 floats
#define F_HH    15816         // H half[64][264] = 8448 floats
#define F_PART  24264         // 64*52 = 3328
#define F_W1F   27592         // 18432 u32
#define F_W2A   46024         // 4096 u32 (32 regions x 32 lane x 4)
#define F_W2B   50120         // 2048 u32 (32 regions x 32 lane x 2)
#define SM_FLOATS 52168
#define SMEM_BYTES (SM_FLOATS * sizeof(float))
#define PSH 152               // P stride (halfs)
#define HSH 264               // H stride (halfs)
#define SPST 52
#define HALO_F 4880           // floats per halo buffer (10 rows x 488)
#define HROW 488              // halo row stride (floats)

__global__ void __launch_bounds__(512, 1)
nca_step_mma(const float* __restrict__ xin, float* __restrict__ xout,
             const float* __restrict__ filt0, const float* __restrict__ filt1,
             const float* __restrict__ b1g,
             const float* __restrict__ w1g, const float* __restrict__ w2g,
             uint32_t key0, uint32_t key1)
{
  extern __shared__ float sm[];
  float*  sfire = sm + F_FIRE;
  float*  sb1   = sm + F_B1;
  float*  sfilt = sm + F_FILT;
  __half* Ph    = (__half*)(sm + F_PH);
  __half* Hh    = (__half*)(sm + F_HH);
  float*  spart = sm + F_PART;
  uint32_t* W1F = (uint32_t*)(sm + F_W1F);
  uint32_t* W2A = (uint32_t*)(sm + F_W2A);
  uint32_t* W2B = (uint32_t*)(sm + F_W2B);

  const uint32_t ph_u32   = smem_u32_of(Ph);
  const uint32_t hh_u32   = smem_u32_of(Hh);
  const uint32_t w1f_u32  = smem_u32_of(W1F);
  const uint32_t w2a_u32  = smem_u32_of(W2A);
  const uint32_t w2b_u32  = smem_u32_of(W2B);
  const uint32_t halo_u32 = smem_u32_of(sm + F_HALO);

  const int tid = threadIdx.x;
  const int wid = tid >> 5, lid = tid & 31;
  const int g = lid >> 2, t = lid & 3;

  // GEMM1 role: ns = N-64 slice (0..3), mh = M-16 chunk (0..3)
  //   (M-16 x N-64 per warp: A loaded once per ks -> halves redundant
  //    ldmatrix traffic vs the old M-32 x N-32 tiling)
  const int ns = wid & 3, mh = wid >> 2;
  // GEMM2 role: mo = M-16 chunk (0..3), nh = N-24 half, kh = K-128 half
  const int mo = wid & 3, nh = (wid >> 2) & 1, kh = wid >> 3;

  // ldmatrix per-lane row mapping
  const int grp = lid >> 3, jj = lid & 7;
  const int rowl = ((grp & 1) << 3) + jj;
  const int koff = (grp >> 1) << 3;

  // ---- once-per-launch: filters, bias, weight-fragment packing ----
  for (int i = tid; i < 864; i += 512) sfilt[i] = (i < 432) ? filt0[i] : filt1[i - 432];
  if (tid < 256) sb1[tid] = b1g[tid];

  for (int idx = tid; idx < 18432; idx += 512) {
    int r = idx & 3, lane = (idx >> 2) & 31, pr = (idx >> 7) & 1, ksns = idx >> 8;
    int ks = ksns >> 3, nss = ksns & 7;
    int gg = lane >> 2, tt = lane & 3;
    int nb = pr * 2 + (r >> 1), j = r & 1;
    int o = nss * 32 + nb * 8 + gg;
    int k = ks * 16 + 2 * tt + j * 8;
    W1F[idx] = packh2(w1g[o * 144 + k], w1g[o * 144 + k + 1]);
  }
  for (int f2 = tid; f2 < 4096; f2 += 512) {
    int r = f2 & 3, lane = (f2 >> 2) & 31, rgn = f2 >> 7;
    int gg = lane >> 2, tt = lane & 3;
    int nb = r >> 1, j = r & 1;
    int c = (rgn & 1) * 24 + nb * 8 + gg;
    int k = (rgn >> 1) * 16 + 2 * tt + j * 8;
    W2A[rgn * 128 + lane * 4 + r] = packh2(w2g[c * 256 + k], w2g[c * 256 + k + 1]);
  }
  for (int f2 = tid; f2 < 2048; f2 += 512) {
    int r = f2 & 1, lane = (f2 >> 1) & 31, rgn = f2 >> 6;
    int gg = lane >> 2, tt = lane & 3;
    int c = (rgn & 1) * 24 + 16 + gg;
    int k = (rgn >> 1) * 16 + 2 * tt + r * 8;
    W2B[rgn * 64 + lane * 2 + r] = packh2(w2g[c * 256 + k], w2g[c * 256 + k + 1]);
  }

  // GEMM1 bias regs: warp covers o in [ns*64, ns*64+64)
  float biasr[8][2];
  #pragma unroll
  for (int nb = 0; nb < 8; nb++) {
    biasr[nb][0] = b1g[ns * 64 + nb * 8 + 2 * t];
    biasr[nb][1] = b1g[ns * 64 + nb * 8 + 2 * t + 1];
  }

  const uint32_t a1base = ph_u32 + (uint32_t)(((mh * 16 + rowl) * PSH + koff) * 2);
  const uint32_t a2base = hh_u32 + (uint32_t)(((mo * 16 + rowl) * HSH + kh * 128 + koff) * 2);
  const uint32_t b1base = w1f_u32 + (uint32_t)(ns * 2048 + lid * 16);   // + ks*8192 + {0,512,1024,1536}
  const uint32_t b2abase = w2a_u32 + (uint32_t)((kh * 16 + nh) * 512 + lid * 16);
  const uint32_t b2bbase = w2b_u32 + (uint32_t)((kh * 16 + nh) * 256 + lid * 8);

  const int niter = (NTILES + (int)gridDim.x - 1) / (int)gridDim.x;

  // ---- prefetch iter-0 halo into buffer 0 ----
  {
    int tile0 = (int)blockIdx.x;
    if (tile0 < NTILES) {
      int bb = tile0 >> 10, y0 = ((tile0 >> 5) & 31) * 8, x0c = (tile0 & 31) * 8;
      const float* xb = xin + (size_t)bb * HWD * HWD * 48;
      for (int i = tid; i < 1200; i += 512) {
        int c4 = i % 12, pos = i / 12, row = pos / 10, col = pos % 10;
        int gy = y0 - 1 + row; gy = (gy < 0) ? -gy : ((gy >= HWD) ? 2 * HWD - 2 - gy : gy);
        int gx = x0c - 1 + col; gx = (gx < 0) ? -gx : ((gx >= HWD) ? 2 * HWD - 2 - gx : gx);
        CP_ASYNC16(halo_u32 + (uint32_t)((row * HROW + col * 48 + c4 * 4) * 4),
                   xb + ((size_t)gy * HWD + gx) * 48 + c4 * 4);
      }
    }
  }
  CP_COMMIT();
  __syncthreads();   // also publishes weights/filters

  int pb = 0;

  for (int iter = 0; iter < niter; iter++) {
    int tile = iter * (int)gridDim.x + (int)blockIdx.x;
    if (tile >= NTILES) break;

    const int bb = tile >> 10;
    const int y0 = ((tile >> 5) & 31) * 8;
    const int x0c = (tile & 31) * 8;

    CP_WAIT0();
    __syncthreads();            // halo[pb] ready; prev epilogue done

    const float* hstage = sm + F_HALO + pb * HALO_F;

    // ---- x-copy: P[pix][k<48] fp16 (from staged float4) ----
    {
      int pix = tid >> 3, c4 = (tid & 7);
      int py = pix >> 3, px = pix & 7;
      int base = (py + 1) * HROW + (px + 1) * 48;
      #pragma unroll
      for (int rep = 0; rep < 2; rep++) {
        int cc4 = c4 + rep * 8;
        if (cc4 < 12) {
          const float4 v = *(const float4*)&hstage[base + cc4 * 4];
          uint2 u; u.x = packh2(v.x, v.y); u.y = packh2(v.z, v.w);
          *(uint2*)&Ph[pix * PSH + cc4 * 4] = u;
        }
      }
    }
    // ---- depthwise convs: 192 merged tasks = (py-pair 0..3, ch 0..47) ----
    if (tid < 192) {
      int ch = tid % 48, pyb = (tid / 48) * 2;
      float v[4][10];
      #pragma unroll
      for (int dy = 0; dy < 4; dy++)
        #pragma unroll
        for (int q = 0; q < 10; q++)
          v[dy][q] = hstage[(pyb + dy) * HROW + q * 48 + ch];
      #pragma unroll
      for (int f = 0; f < 2; f++) {
        const float* cf = sfilt + (f * 48 + ch) * 9;
        float w[9];
        #pragma unroll
        for (int e = 0; e < 9; e++) w[e] = cf[e];
        int K = 48 + f * 48 + ch;
        #pragma unroll
        for (int p2 = 0; p2 < 2; p2++) {
          float acc[8] = {0.f,0.f,0.f,0.f,0.f,0.f,0.f,0.f};
          #pragma unroll
          for (int dy = 0; dy < 3; dy++)
            #pragma unroll
            for (int dx = 0; dx < 3; dx++) {
              float ww = w[dy * 3 + dx];
              #pragma unroll
              for (int i = 0; i < 8; i++)
                acc[i] = fmaf(v[p2 + dy][i + dx], ww, acc[i]);
            }
          #pragma unroll
          for (int i = 0; i < 8; i++)
            Ph[((pyb + p2) * 8 + i) * PSH + K] = __float2half_rn(acc[i]);
        }
      }
    }
    // ---- fire mask (warps 14-15, idle in conv) ----
    if (tid >= 448) {
      int p = tid - 448;
      int py = p >> 3, px = p & 7;
      uint32_t n = ((uint32_t)bb * HWD + (uint32_t)(y0 + py)) * HWD + (uint32_t)(x0c + px);
      uint32_t r0, r1;
      threefry2x32(key0, key1, 0u, n, r0, r1);
      float u = __uint_as_float(((r0 ^ r1) >> 9) | 0x3f800000u) - 1.0f;
      sfire[p] = (u > 0.5f) ? 1.0f : 0.0f;
    }

    // ---- prefetch next tile's halo into buffer pb^1 (overlaps GEMMs) ----
    {
      int ntile = tile + (int)gridDim.x;
      if (ntile < NTILES) {
        int nbb = ntile >> 10, ny0 = ((ntile >> 5) & 31) * 8, nx0 = (ntile & 31) * 8;
        const float* nxb = xin + (size_t)nbb * HWD * HWD * 48;
        uint32_t dbase = halo_u32 + (uint32_t)((pb ^ 1) * HALO_F * 4);
        for (int i = tid; i < 1200; i += 512) {
          int c4 = i % 12, pos = i / 12, row = pos / 10, col = pos % 10;
          int gy = ny0 - 1 + row; gy = (gy < 0) ? -gy : ((gy >= HWD) ? 2 * HWD - 2 - gy : gy);
          int gx = nx0 - 1 + col; gx = (gx < 0) ? -gx : ((gx >= HWD) ? 2 * HWD - 2 - gx : gx);
          CP_ASYNC16(dbase + (uint32_t)((row * HROW + col * 48 + c4 * 4) * 4),
                     nxb + ((size_t)gy * HWD + gx) * 48 + c4 * 4);
        }
      }
    }
    CP_COMMIT();
    __syncthreads();            // Ph + fire ready

    // ---- GEMM1: warp = (M-16 x N-64), 9 ksteps of k16 ----
    {
      float acc[8][4];
      #pragma unroll
      for (int nb = 0; nb < 8; nb++)
        #pragma unroll
        for (int e = 0; e < 4; e++) acc[nb][e] = 0.f;

      #pragma unroll
      for (int ks = 0; ks < 9; ks++) {
        uint32_t b[8][2];
        LDS_V4(b[0][0], b[0][1], b[1][0], b[1][1], b1base + ks * 8192);
        LDS_V4(b[2][0], b[2][1], b[3][0], b[3][1], b1base + ks * 8192 + 512);
        LDS_V4(b[4][0], b[4][1], b[5][0], b[5][1], b1base + ks * 8192 + 1024);
        LDS_V4(b[6][0], b[6][1], b[7][0], b[7][1], b1base + ks * 8192 + 1536);
        uint32_t a0, a1, a2, a3;
        LDMATRIX_X4(a0, a1, a2, a3, a1base + ks * 32);
        #pragma unroll
        for (int nb = 0; nb < 8; nb++)
          mma_f16(acc[nb], a0, a1, a2, a3, b[nb][0], b[nb][1]);
      }
      // epilogue1: bias + leaky -> H fp16
      #pragma unroll
      for (int nb = 0; nb < 8; nb++) {
        int row = mh * 16 + g;
        int col = ns * 64 + nb * 8 + 2 * t;
        float v0 = acc[nb][0] + biasr[nb][0];
        float v1 = acc[nb][1] + biasr[nb][1];
        v0 = (v0 > 0.f) ? v0 : 0.01f * v0;
        v1 = (v1 > 0.f) ? v1 : 0.01f * v1;
        *(__half2*)&Hh[row * HSH + col] = __floats2half2_rn(v0, v1);
        float v2 = acc[nb][2] + biasr[nb][0];
        float v3 = acc[nb][3] + biasr[nb][1];
        v2 = (v2 > 0.f) ? v2 : 0.01f * v2;
        v3 = (v3 > 0.f) ? v3 : 0.01f * v3;
        *(__half2*)&Hh[(row + 8) * HSH + col] = __floats2half2_rn(v2, v3);
      }
    }
    __syncthreads();            // H ready

    // ---- GEMM2: warp = (M-16, N-24, K-128 half); 8 ksteps ----
    float acc2[3][4];
    #pragma unroll
    for (int nb = 0; nb < 3; nb++)
      #pragma unroll
      for (int e = 0; e < 4; e++) acc2[nb][e] = 0.f;

    #pragma unroll
    for (int ks = 0; ks < 8; ks++) {
      uint32_t b2[3][2];
      LDS_V4(b2[0][0], b2[0][1], b2[1][0], b2[1][1], b2abase + ks * 1024);
      LDS_V2(b2[2][0], b2[2][1], b2bbase + ks * 512);
      uint32_t a0, a1, a2, a3;
      LDMATRIX_X4(a0, a1, a2, a3, a2base + ks * 32);
      #pragma unroll
      for (int nb = 0; nb < 3; nb++)
        mma_f16(acc2[nb], a0, a1, a2, a3, b2[nb][0], b2[nb][1]);
    }

    // kh=1 warps publish partials
    if (kh == 1) {
      #pragma unroll
      for (int nb = 0; nb < 3; nb++) {
        int c = nh * 24 + nb * 8 + 2 * t;
        *(float2*)&spart[(mo * 16 + g) * SPST + c]     = make_float2(acc2[nb][0], acc2[nb][1]);
        *(float2*)&spart[(mo * 16 + g + 8) * SPST + c] = make_float2(acc2[nb][2], acc2[nb][3]);
      }
    }
    __syncthreads();

    // kh=0 warps: reduce + fire + masked residual -> gmem
    if (kh == 0) {
      #pragma unroll
      for (int nb = 0; nb < 3; nb++) {
        int c = nh * 24 + nb * 8 + 2 * t;
        #pragma unroll
        for (int hf = 0; hf < 2; hf++) {
          int pix = mo * 16 + g + hf * 8;
          int py = pix >> 3, px = pix & 7;
          float fire = sfire[pix];
          float2 pp = *(const float2*)&spart[pix * SPST + c];
          float d0 = acc2[nb][hf * 2 + 0] + pp.x;
          float d1 = acc2[nb][hf * 2 + 1] + pp.y;
          int hb = (py + 1) * HROW + (px + 1) * 48;
          float xo0 = hstage[hb + c];
          float xo1 = hstage[hb + c + 1];
          float o0 = xo0 + ((c     >= 3) ? fire * d0 : 0.f);
          float o1 = xo1 + ((c + 1 >= 3) ? fire * d1 : 0.f);
          float* op = xout + (((size_t)bb * HWD + (y0 + py)) * HWD + (x0c + px)) * 48 + c;
          *(float2*)op = make_float2(o0, o1);
        }
      }
    }
    pb ^= 1;
    // loop-top wait+sync orders epilogue reads before next prefetch overwrite
  }
}

// ---------------- launcher ----------------
extern "C" void kernel_launch(void* const* d_in, const int* in_sizes, int n_in,
                              void* d_out, int out_size)
{
  const float* x     = (const float*)d_in[0];
  const float* filt0 = (const float*)d_in[1];
  const float* filt1 = (const float*)d_in[2];
  const float* w1    = (const float*)d_in[3];
  const float* b1    = (const float*)d_in[4];
  const float* w2    = (const float*)d_in[5];

  float* xbuf = nullptr;
  cudaGetSymbolAddress((void**)&xbuf, g_xbuf);
  float* outp = (float*)d_out;

  int nsm = 148;
  cudaDeviceGetAttribute(&nsm, cudaDevAttrMultiProcessorCount, 0);

  cudaFuncSetAttribute(nca_step_mma, cudaFuncAttributeMaxDynamicSharedMemorySize,
                       (int)SMEM_BYTES);

  const float* src = x;
  for (int i = 0; i < 4; i++) {
    uint32_t f0, f1; threefry2x32(0u, 42u, 0u, (uint32_t)i, f0, f1);
    uint32_t a0, a1; threefry2x32(f0, f1, 0u, 0u, a0, a1);
    float* dst = (i & 1) ? outp : xbuf;
    if (i == 3) dst = outp;
    nca_step_mma<<<nsm, 512, SMEM_BYTES>>>(src, dst, filt0, filt1, b1, w1, w2,
                                           a0, a1);
    src = dst;
  }
}

// round 16
// speedup vs baseline: 1.0277x; 1.0277x over previous
#include <cuda_runtime.h>
#include <cuda_fp16.h>
#include <cstdint>

#define HWD 256
#define NTILES 8192      // 8 batches * 32 * 32 tiles of 8x8 pixels

// ---------------- device scratch ----------------
__device__ float g_xbuf[(size_t)8 * HWD * HWD * 48];

// ---------------- threefry2x32 (exact JAX, 20 rounds) ----------------
__host__ __device__ __forceinline__ void threefry2x32(
    uint32_t k0, uint32_t k1, uint32_t x0, uint32_t x1, uint32_t& o0, uint32_t& o1) {
  uint32_t ks2 = k0 ^ k1 ^ 0x1BD11BDAu;
  uint32_t v0 = x0 + k0, v1 = x1 + k1;
#define TF_ROTL(v, r) (((v) << (r)) | ((v) >> (32 - (r))))
#define TF_RND(r) { v0 += v1; v1 = TF_ROTL(v1, r); v1 ^= v0; }
  TF_RND(13) TF_RND(15) TF_RND(26) TF_RND(6)
  v0 += k1;  v1 += ks2 + 1u;
  TF_RND(17) TF_RND(29) TF_RND(16) TF_RND(24)
  v0 += ks2; v1 += k0 + 2u;
  TF_RND(13) TF_RND(15) TF_RND(26) TF_RND(6)
  v0 += k0;  v1 += k1 + 3u;
  TF_RND(17) TF_RND(29) TF_RND(16) TF_RND(24)
  v0 += k1;  v1 += ks2 + 4u;
  TF_RND(13) TF_RND(15) TF_RND(26) TF_RND(6)
  v0 += ks2; v1 += k0 + 5u;
#undef TF_RND
#undef TF_ROTL
  o0 = v0; o1 = v1;
}

// ---------------- helpers ----------------
__device__ __forceinline__ void mma_f16(float* c, uint32_t a0, uint32_t a1,
                                        uint32_t a2, uint32_t a3,
                                        uint32_t b0, uint32_t b1) {
  asm volatile(
    "mma.sync.aligned.m16n8k16.row.col.f32.f16.f16.f32 "
    "{%0,%1,%2,%3},{%4,%5,%6,%7},{%8,%9},{%0,%1,%2,%3};"
    : "+f"(c[0]), "+f"(c[1]), "+f"(c[2]), "+f"(c[3])
    : "r"(a0), "r"(a1), "r"(a2), "r"(a3), "r"(b0), "r"(b1));
}
#define LDMATRIX_X4(r0, r1, r2, r3, addr) \
  asm volatile("ldmatrix.sync.aligned.m8n8.x4.shared.b16 {%0,%1,%2,%3},[%4];" \
    : "=r"(r0), "=r"(r1), "=r"(r2), "=r"(r3) : "r"(addr))
#define LDS_V4(r0, r1, r2, r3, addr) \
  asm volatile("ld.shared.v4.u32 {%0,%1,%2,%3},[%4];" \
    : "=r"(r0), "=r"(r1), "=r"(r2), "=r"(r3) : "r"(addr))
#define LDS_V2(r0, r1, addr) \
  asm volatile("ld.shared.v2.u32 {%0,%1},[%2];" \
    : "=r"(r0), "=r"(r1) : "r"(addr))
#define CP_ASYNC16(dst, src) \
  asm volatile("cp.async.ca.shared.global [%0], [%1], 16;" :: "r"(dst), "l"(src))
#define CP_COMMIT() asm volatile("cp.async.commit_group;" ::: "memory")
#define CP_WAIT0()  asm volatile("cp.async.wait_group 0;" ::: "memory")

__device__ __forceinline__ uint32_t smem_u32_of(const void* p) {
  uint32_t a;
  asm("{ .reg .u64 t; cvta.to.shared.u64 t, %1; cvt.u32.u64 %0, t; }" : "=r"(a) : "l"(p));
  return a;
}
__device__ __forceinline__ uint32_t packh2(float a, float b) {
  __half2 h = __floats2half2_rn(a, b);
  return *(uint32_t*)&h;
}

// ---------------- shared memory layout (float offsets) ----------------
#define F_FIRE  8             // 2 x 64 (double-buffered fire mask)
#define F_B1    136           // 256
#define F_FILT  392           // 864
#define F_HALO  1256          // 2 x 4880 = 9760 (double-buffered staging)
#define F_PH    11016         // P half[64][152] = 4864 floats
#define F_HH    15880         // H half[64][264] = 8448 floats
#define F_PART  24328         // 64*52 = 3328
#define F_W1F   27656         // 18432 u32
#define F_W2A   46088         // 4096 u32
#define F_W2B   50184         // 2048 u32
#define SM_FLOATS 52232
#define SMEM_BYTES (SM_FLOATS * sizeof(float))
#define PSH 152               // P stride (halfs)
#define HSH 264               // H stride (halfs)
#define SPST 52
#define HALO_F 4880           // floats per halo buffer (10 rows x 488)
#define HROW 488              // halo row stride (floats)

__global__ void __launch_bounds__(512, 1)
nca_step_mma(const float* __restrict__ xin, float* __restrict__ xout,
             const float* __restrict__ filt0, const float* __restrict__ filt1,
             const float* __restrict__ b1g,
             const float* __restrict__ w1g, const float* __restrict__ w2g,
             uint32_t key0, uint32_t key1)
{
  extern __shared__ float sm[];
  float*  sfire = sm + F_FIRE;      // [2][64]
  float*  sb1   = sm + F_B1;
  float*  sfilt = sm + F_FILT;
  __half* Ph    = (__half*)(sm + F_PH);
  __half* Hh    = (__half*)(sm + F_HH);
  float*  spart = sm + F_PART;
  uint32_t* W1F = (uint32_t*)(sm + F_W1F);
  uint32_t* W2A = (uint32_t*)(sm + F_W2A);
  uint32_t* W2B = (uint32_t*)(sm + F_W2B);

  const uint32_t ph_u32   = smem_u32_of(Ph);
  const uint32_t hh_u32   = smem_u32_of(Hh);
  const uint32_t w1f_u32  = smem_u32_of(W1F);
  const uint32_t w2a_u32  = smem_u32_of(W2A);
  const uint32_t w2b_u32  = smem_u32_of(W2B);
  const uint32_t halo_u32 = smem_u32_of(sm + F_HALO);

  const int tid = threadIdx.x;
  const int wid = tid >> 5, lid = tid & 31;
  const int g = lid >> 2, t = lid & 3;

  // GEMM1 role: ns = N-32 slice (0..7), mh = M-32 half (0..1)  [optimal tiling]
  const int ns = wid & 7, mh = wid >> 3;
  // GEMM2 role: mo = M-16 chunk (0..3), nh = N-24 half, kh = K-128 half
  const int mo = wid & 3, nh = (wid >> 2) & 1, kh = wid >> 3;

  // ldmatrix per-lane row mapping
  const int grp = lid >> 3, jj = lid & 7;
  const int rowl = ((grp & 1) << 3) + jj;
  const int koff = (grp >> 1) << 3;

  // ---- once-per-launch: filters, bias, weight-fragment packing ----
  for (int i = tid; i < 864; i += 512) sfilt[i] = (i < 432) ? filt0[i] : filt1[i - 432];
  if (tid < 256) sb1[tid] = b1g[tid];

  for (int idx = tid; idx < 18432; idx += 512) {
    int r = idx & 3, lane = (idx >> 2) & 31, pr = (idx >> 7) & 1, ksns = idx >> 8;
    int ks = ksns >> 3, nss = ksns & 7;
    int gg = lane >> 2, tt = lane & 3;
    int nb = pr * 2 + (r >> 1), j = r & 1;
    int o = nss * 32 + nb * 8 + gg;
    int k = ks * 16 + 2 * tt + j * 8;
    W1F[idx] = packh2(w1g[o * 144 + k], w1g[o * 144 + k + 1]);
  }
  for (int f2 = tid; f2 < 4096; f2 += 512) {
    int r = f2 & 3, lane = (f2 >> 2) & 31, rgn = f2 >> 7;
    int gg = lane >> 2, tt = lane & 3;
    int nb = r >> 1, j = r & 1;
    int c = (rgn & 1) * 24 + nb * 8 + gg;
    int k = (rgn >> 1) * 16 + 2 * tt + j * 8;
    W2A[rgn * 128 + lane * 4 + r] = packh2(w2g[c * 256 + k], w2g[c * 256 + k + 1]);
  }
  for (int f2 = tid; f2 < 2048; f2 += 512) {
    int r = f2 & 1, lane = (f2 >> 1) & 31, rgn = f2 >> 6;
    int gg = lane >> 2, tt = lane & 3;
    int c = (rgn & 1) * 24 + 16 + gg;
    int k = (rgn >> 1) * 16 + 2 * tt + r * 8;
    W2B[rgn * 64 + lane * 2 + r] = packh2(w2g[c * 256 + k], w2g[c * 256 + k + 1]);
  }

  uint32_t a1base[2];
  #pragma unroll
  for (int mc = 0; mc < 2; mc++)
    a1base[mc] = ph_u32 + (uint32_t)(((mh * 32 + mc * 16 + rowl) * PSH + koff) * 2);
  const uint32_t a2base = hh_u32 + (uint32_t)(((mo * 16 + rowl) * HSH + kh * 128 + koff) * 2);
  const uint32_t b1base = w1f_u32 + (uint32_t)(ns * 2 * 512 + lid * 16);
  const uint32_t b2abase = w2a_u32 + (uint32_t)((kh * 16 + nh) * 512 + lid * 16);
  const uint32_t b2bbase = w2b_u32 + (uint32_t)((kh * 16 + nh) * 256 + lid * 8);

  const int niter = (NTILES + (int)gridDim.x - 1) / (int)gridDim.x;

  // ================= helpers as lambdas =================
  auto issue_halo = [&](int tt2, int buf) {
    int bb = tt2 >> 10, y0 = ((tt2 >> 5) & 31) * 8, x0c = (tt2 & 31) * 8;
    const float* xb = xin + (size_t)bb * HWD * HWD * 48;
    uint32_t dbase = halo_u32 + (uint32_t)(buf * HALO_F * 4);
    for (int i = tid; i < 1200; i += 512) {
      int c4 = i % 12, pos = i / 12, row = pos / 10, col = pos % 10;
      int gy = y0 - 1 + row; gy = (gy < 0) ? -gy : ((gy >= HWD) ? 2 * HWD - 2 - gy : gy);
      int gx = x0c - 1 + col; gx = (gx < 0) ? -gx : ((gx >= HWD) ? 2 * HWD - 2 - gx : gx);
      CP_ASYNC16(dbase + (uint32_t)((row * HROW + col * 48 + c4 * 4) * 4),
                 xb + ((size_t)gy * HWD + gx) * 48 + c4 * 4);
    }
  };

  auto build_tile = [&](int tt2, int buf, int fbuf) {
    const float* hs = sm + F_HALO + buf * HALO_F;
    // x-copy: P[pix][k<48]
    {
      int pix = tid >> 3, c4 = (tid & 7);
      int py = pix >> 3, px = pix & 7;
      int base = (py + 1) * HROW + (px + 1) * 48;
      #pragma unroll
      for (int rep = 0; rep < 2; rep++) {
        int cc4 = c4 + rep * 8;
        if (cc4 < 12) {
          const float4 v = *(const float4*)&hs[base + cc4 * 4];
          uint2 u; u.x = packh2(v.x, v.y); u.y = packh2(v.z, v.w);
          *(uint2*)&Ph[pix * PSH + cc4 * 4] = u;
        }
      }
    }
    // depthwise convs: 192 merged tasks
    if (tid < 192) {
      int ch = tid % 48, pyb = (tid / 48) * 2;
      float v[4][10];
      #pragma unroll
      for (int dy = 0; dy < 4; dy++)
        #pragma unroll
        for (int q = 0; q < 10; q++)
          v[dy][q] = hs[(pyb + dy) * HROW + q * 48 + ch];
      #pragma unroll
      for (int f = 0; f < 2; f++) {
        const float* cf = sfilt + (f * 48 + ch) * 9;
        float w[9];
        #pragma unroll
        for (int e = 0; e < 9; e++) w[e] = cf[e];
        int K = 48 + f * 48 + ch;
        #pragma unroll
        for (int p2 = 0; p2 < 2; p2++) {
          float acc[8] = {0.f,0.f,0.f,0.f,0.f,0.f,0.f,0.f};
          #pragma unroll
          for (int dy = 0; dy < 3; dy++)
            #pragma unroll
            for (int dx = 0; dx < 3; dx++) {
              float ww = w[dy * 3 + dx];
              #pragma unroll
              for (int i = 0; i < 8; i++)
                acc[i] = fmaf(v[p2 + dy][i + dx], ww, acc[i]);
            }
          #pragma unroll
          for (int i = 0; i < 8; i++)
            Ph[((pyb + p2) * 8 + i) * PSH + K] = __float2half_rn(acc[i]);
        }
      }
    }
    // fire mask (warps 14-15)
    if (tid >= 448) {
      int p = tid - 448;
      int bb = tt2 >> 10, y0 = ((tt2 >> 5) & 31) * 8, x0c = (tt2 & 31) * 8;
      int py = p >> 3, px = p & 7;
      uint32_t n = ((uint32_t)bb * HWD + (uint32_t)(y0 + py)) * HWD + (uint32_t)(x0c + px);
      uint32_t r0, r1;
      threefry2x32(key0, key1, 0u, n, r0, r1);
      float u = __uint_as_float(((r0 ^ r1) >> 9) | 0x3f800000u) - 1.0f;
      sfire[fbuf * 64 + p] = (u > 0.5f) ? 1.0f : 0.0f;
    }
  };

  // ================= prologue: tile0 =================
  {
    int tile0 = (int)blockIdx.x;
    if (tile0 < NTILES) issue_halo(tile0, 0);
    CP_COMMIT();
    CP_WAIT0();
    __syncthreads();             // halo(t0) + weights/filters visible
    if (tile0 < NTILES) build_tile(tile0, 0, 0);
  }
  int pb = 0, ff = 0;

  // ================= pipelined tile loop =================
  for (int iter = 0; iter < niter; iter++) {
    int tile = iter * (int)gridDim.x + (int)blockIdx.x;
    if (tile >= NTILES) break;
    int ntile = tile + (int)gridDim.x;

    const int bb = tile >> 10;
    const int y0 = ((tile >> 5) & 31) * 8;
    const int x0c = (tile & 31) * 8;

    // ---- interval A: Ph(tile)/fire ready; issue prefetch(n+1); GEMM1 ----
    __syncthreads();
    if (ntile < NTILES) issue_halo(ntile, pb ^ 1);
    CP_COMMIT();

    {
      float acc[2][4][4];
      #pragma unroll
      for (int mc = 0; mc < 2; mc++)
        #pragma unroll
        for (int nb = 0; nb < 4; nb++)
          #pragma unroll
          for (int e = 0; e < 4; e++) acc[mc][nb][e] = 0.f;

      #pragma unroll
      for (int ks = 0; ks < 9; ks++) {
        uint32_t b[4][2];
        LDS_V4(b[0][0], b[0][1], b[1][0], b[1][1], b1base + ks * 8192);
        LDS_V4(b[2][0], b[2][1], b[3][0], b[3][1], b1base + ks * 8192 + 512);
        #pragma unroll
        for (int mc = 0; mc < 2; mc++) {
          uint32_t a0, a1, a2, a3;
          LDMATRIX_X4(a0, a1, a2, a3, a1base[mc] + ks * 32);
          #pragma unroll
          for (int nb = 0; nb < 4; nb++)
            mma_f16(acc[mc][nb], a0, a1, a2, a3, b[nb][0], b[nb][1]);
        }
      }
      // epilogue1: bias + leaky -> H fp16
      #pragma unroll
      for (int mc = 0; mc < 2; mc++)
        #pragma unroll
        for (int nb = 0; nb < 4; nb++) {
          int row = mh * 32 + mc * 16 + g;
          int col = ns * 32 + nb * 8 + 2 * t;
          float b0 = sb1[col], b1v = sb1[col + 1];
          float v0 = acc[mc][nb][0] + b0;
          float v1 = acc[mc][nb][1] + b1v;
          v0 = (v0 > 0.f) ? v0 : 0.01f * v0;
          v1 = (v1 > 0.f) ? v1 : 0.01f * v1;
          *(__half2*)&Hh[row * HSH + col] = __floats2half2_rn(v0, v1);
          float v2 = acc[mc][nb][2] + b0;
          float v3 = acc[mc][nb][3] + b1v;
          v2 = (v2 > 0.f) ? v2 : 0.01f * v2;
          v3 = (v3 > 0.f) ? v3 : 0.01f * v3;
          *(__half2*)&Hh[(row + 8) * HSH + col] = __floats2half2_rn(v2, v3);
        }
    }

    // ---- interval B: Hh ready; conv(n+1) overlapped with GEMM2(tile) ----
    CP_WAIT0();
    __syncthreads();            // Hh visible + halo(n+1) visible; Ph free

    if (ntile < NTILES) build_tile(ntile, pb ^ 1, ff ^ 1);

    float acc2[3][4];
    #pragma unroll
    for (int nb = 0; nb < 3; nb++)
      #pragma unroll
      for (int e = 0; e < 4; e++) acc2[nb][e] = 0.f;

    #pragma unroll
    for (int ks = 0; ks < 8; ks++) {
      uint32_t b2[3][2];
      LDS_V4(b2[0][0], b2[0][1], b2[1][0], b2[1][1], b2abase + ks * 1024);
      LDS_V2(b2[2][0], b2[2][1], b2bbase + ks * 512);
      uint32_t a0, a1, a2, a3;
      LDMATRIX_X4(a0, a1, a2, a3, a2base + ks * 32);
      #pragma unroll
      for (int nb = 0; nb < 3; nb++)
        mma_f16(acc2[nb], a0, a1, a2, a3, b2[nb][0], b2[nb][1]);
    }
    if (kh == 1) {
      #pragma unroll
      for (int nb = 0; nb < 3; nb++) {
        int c = nh * 24 + nb * 8 + 2 * t;
        *(float2*)&spart[(mo * 16 + g) * SPST + c]     = make_float2(acc2[nb][0], acc2[nb][1]);
        *(float2*)&spart[(mo * 16 + g + 8) * SPST + c] = make_float2(acc2[nb][2], acc2[nb][3]);
      }
    }

    // ---- interval C: reduce + epilogue2(tile) ----
    __syncthreads();
    if (kh == 0) {
      const float* hs = sm + F_HALO + pb * HALO_F;
      #pragma unroll
      for (int nb = 0; nb < 3; nb++) {
        int c = nh * 24 + nb * 8 + 2 * t;
        #pragma unroll
        for (int hf = 0; hf < 2; hf++) {
          int pix = mo * 16 + g + hf * 8;
          int py = pix >> 3, px = pix & 7;
          float fire = sfire[ff * 64 + pix];
          float2 pp = *(const float2*)&spart[pix * SPST + c];
          float d0 = acc2[nb][hf * 2 + 0] + pp.x;
          float d1 = acc2[nb][hf * 2 + 1] + pp.y;
          int hb = (py + 1) * HROW + (px + 1) * 48;
          float xo0 = hs[hb + c];
          float xo1 = hs[hb + c + 1];
          float o0 = xo0 + ((c     >= 3) ? fire * d0 : 0.f);
          float o1 = xo1 + ((c + 1 >= 3) ? fire * d1 : 0.f);
          float* op = xout + (((size_t)bb * HWD + (y0 + py)) * HWD + (x0c + px)) * 48 + c;
          *(float2*)op = make_float2(o0, o1);
        }
      }
    }
    pb ^= 1; ff ^= 1;
    // loop-top sync (interval A) orders epilogue2 reads before next prefetch
  }
}

// ---------------- launcher ----------------
extern "C" void kernel_launch(void* const* d_in, const int* in_sizes, int n_in,
                              void* d_out, int out_size)
{
  const float* x     = (const float*)d_in[0];
  const float* filt0 = (const float*)d_in[1];
  const float* filt1 = (const float*)d_in[2];
  const float* w1    = (const float*)d_in[3];
  const float* b1    = (const float*)d_in[4];
  const float* w2    = (const float*)d_in[5];

  float* xbuf = nullptr;
  cudaGetSymbolAddress((void**)&xbuf, g_xbuf);
  float* outp = (float*)d_out;

  int nsm = 148;
  cudaDeviceGetAttribute(&nsm, cudaDevAttrMultiProcessorCount, 0);

  cudaFuncSetAttribute(nca_step_mma, cudaFuncAttributeMaxDynamicSharedMemorySize,
                       (int)SMEM_BYTES);

  const float* src = x;
  for (int i = 0; i < 4; i++) {
    uint32_t f0, f1; threefry2x32(0u, 42u, 0u, (uint32_t)i, f0, f1);
    uint32_t a0, a1; threefry2x32(f0, f1, 0u, 0u, a0, a1);
    float* dst = (i & 1) ? outp : xbuf;
    if (i == 3) dst = outp;
    nca_step_mma<<<nsm, 512, SMEM_BYTES>>>(src, dst, filt0, filt1, b1, w1, w2,
                                           a0, a1);
    src = dst;
  }
}

// round 17
// speedup vs baseline: 1.0916x; 1.0622x over previous
#include <cuda_runtime.h>
#include <cuda_fp16.h>
#include <cstdint>

#define HWD 256
#define NTILES 8192      // 8 batches * 32 * 32 tiles of 8x8 pixels

// ---------------- device scratch ----------------
__device__ float g_xbuf[(size_t)8 * HWD * HWD * 48];

// ---------------- threefry2x32 (exact JAX, 20 rounds) ----------------
__host__ __device__ __forceinline__ void threefry2x32(
    uint32_t k0, uint32_t k1, uint32_t x0, uint32_t x1, uint32_t& o0, uint32_t& o1) {
  uint32_t ks2 = k0 ^ k1 ^ 0x1BD11BDAu;
  uint32_t v0 = x0 + k0, v1 = x1 + k1;
#define TF_ROTL(v, r) (((v) << (r)) | ((v) >> (32 - (r))))
#define TF_RND(r) { v0 += v1; v1 = TF_ROTL(v1, r); v1 ^= v0; }
  TF_RND(13) TF_RND(15) TF_RND(26) TF_RND(6)
  v0 += k1;  v1 += ks2 + 1u;
  TF_RND(17) TF_RND(29) TF_RND(16) TF_RND(24)
  v0 += ks2; v1 += k0 + 2u;
  TF_RND(13) TF_RND(15) TF_RND(26) TF_RND(6)
  v0 += k0;  v1 += k1 + 3u;
  TF_RND(17) TF_RND(29) TF_RND(16) TF_RND(24)
  v0 += k1;  v1 += ks2 + 4u;
  TF_RND(13) TF_RND(15) TF_RND(26) TF_RND(6)
  v0 += ks2; v1 += k0 + 5u;
#undef TF_RND
#undef TF_ROTL
  o0 = v0; o1 = v1;
}

// ---------------- helpers ----------------
__device__ __forceinline__ void mma_f16(float* c, uint32_t a0, uint32_t a1,
                                        uint32_t a2, uint32_t a3,
                                        uint32_t b0, uint32_t b1) {
  asm volatile(
    "mma.sync.aligned.m16n8k16.row.col.f32.f16.f16.f32 "
    "{%0,%1,%2,%3},{%4,%5,%6,%7},{%8,%9},{%0,%1,%2,%3};"
    : "+f"(c[0]), "+f"(c[1]), "+f"(c[2]), "+f"(c[3])
    : "r"(a0), "r"(a1), "r"(a2), "r"(a3), "r"(b0), "r"(b1));
}
#define LDMATRIX_X4(r0, r1, r2, r3, addr) \
  asm volatile("ldmatrix.sync.aligned.m8n8.x4.shared.b16 {%0,%1,%2,%3},[%4];" \
    : "=r"(r0), "=r"(r1), "=r"(r2), "=r"(r3) : "r"(addr))
#define LDS_V4(r0, r1, r2, r3, addr) \
  asm volatile("ld.shared.v4.u32 {%0,%1,%2,%3},[%4];" \
    : "=r"(r0), "=r"(r1), "=r"(r2), "=r"(r3) : "r"(addr))
#define LDS_V2(r0, r1, addr) \
  asm volatile("ld.shared.v2.u32 {%0,%1},[%2];" \
    : "=r"(r0), "=r"(r1) : "r"(addr))
#define CP_ASYNC16(dst, src) \
  asm volatile("cp.async.ca.shared.global [%0], [%1], 16;" :: "r"(dst), "l"(src))
#define CP_COMMIT() asm volatile("cp.async.commit_group;" ::: "memory")
#define CP_WAIT0()  asm volatile("cp.async.wait_group 0;" ::: "memory")

__device__ __forceinline__ uint32_t smem_u32_of(const void* p) {
  uint32_t a;
  asm("{ .reg .u64 t; cvta.to.shared.u64 t, %1; cvt.u32.u64 %0, t; }" : "=r"(a) : "l"(p));
  return a;
}
__device__ __forceinline__ uint32_t packh2(float a, float b) {
  __half2 h = __floats2half2_rn(a, b);
  return *(uint32_t*)&h;
}

// ---------------- shared memory layout (float offsets) ----------------
#define F_FIRE  8             // 2 x 64 (double-buffered fire mask)
#define F_B1    136           // 256
#define F_FILT  392           // 864
#define F_HALO  1256          // 2 x 4880 = 9760 (double-buffered staging)
#define F_PH    11016         // P half[64][152] = 4864 floats
#define F_HH    15880         // H half[64][264] = 8448 floats
#define F_W1F   24328         // 18432 u32
#define F_W2A   42760         // 4096 u32
#define F_W2B   46856         // 2048 u32
#define SM_FLOATS 48904
#define SMEM_BYTES (SM_FLOATS * sizeof(float))
#define PSH 152               // P stride (halfs)
#define HSH 264               // H stride (halfs)
#define HALO_F 4880           // floats per halo buffer (10 rows x 488)
#define HROW 488              // halo row stride (floats)

__global__ void __launch_bounds__(512, 1)
nca_step_mma(const float* __restrict__ xin, float* __restrict__ xout,
             const float* __restrict__ filt0, const float* __restrict__ filt1,
             const float* __restrict__ b1g,
             const float* __restrict__ w1g, const float* __restrict__ w2g,
             uint32_t key0, uint32_t key1)
{
  extern __shared__ float sm[];
  float*  sfire = sm + F_FIRE;      // [2][64]
  float*  sb1   = sm + F_B1;
  float*  sfilt = sm + F_FILT;
  __half* Ph    = (__half*)(sm + F_PH);
  __half* Hh    = (__half*)(sm + F_HH);
  uint32_t* W1F = (uint32_t*)(sm + F_W1F);
  uint32_t* W2A = (uint32_t*)(sm + F_W2A);
  uint32_t* W2B = (uint32_t*)(sm + F_W2B);

  const uint32_t ph_u32   = smem_u32_of(Ph);
  const uint32_t hh_u32   = smem_u32_of(Hh);
  const uint32_t w1f_u32  = smem_u32_of(W1F);
  const uint32_t w2a_u32  = smem_u32_of(W2A);
  const uint32_t w2b_u32  = smem_u32_of(W2B);
  const uint32_t halo_u32 = smem_u32_of(sm + F_HALO);

  const int tid = threadIdx.x;
  const int wid = tid >> 5, lid = tid & 31;
  const int g = lid >> 2, t = lid & 3;

  // GEMM1 role (all 16 warps): ns = N-32 slice (0..7), mh = M-32 half (0..1)
  const int ns = wid & 7, mh = wid >> 3;
  // GEMM2 role (warps 8..15 only): q = wid-8 -> mo = q&3 (M-16), nh = q>>2 (N-24)
  const int q2 = wid - 8, mo = q2 & 3, nh = (q2 >> 2) & 1;

  // ldmatrix per-lane row mapping
  const int grp = lid >> 3, jj = lid & 7;
  const int rowl = ((grp & 1) << 3) + jj;
  const int koff = (grp >> 1) << 3;

  // ---- once-per-launch: filters, bias, weight-fragment packing ----
  for (int i = tid; i < 864; i += 512) sfilt[i] = (i < 432) ? filt0[i] : filt1[i - 432];
  if (tid < 256) sb1[tid] = b1g[tid];

  for (int idx = tid; idx < 18432; idx += 512) {
    int r = idx & 3, lane = (idx >> 2) & 31, pr = (idx >> 7) & 1, ksns = idx >> 8;
    int ks = ksns >> 3, nss = ksns & 7;
    int gg = lane >> 2, tt = lane & 3;
    int nb = pr * 2 + (r >> 1), j = r & 1;
    int o = nss * 32 + nb * 8 + gg;
    int k = ks * 16 + 2 * tt + j * 8;
    W1F[idx] = packh2(w1g[o * 144 + k], w1g[o * 144 + k + 1]);
  }
  for (int f2 = tid; f2 < 4096; f2 += 512) {
    int r = f2 & 3, lane = (f2 >> 2) & 31, rgn = f2 >> 7;   // rgn = ksg*2 + nh
    int gg = lane >> 2, tt = lane & 3;
    int nb = r >> 1, j = r & 1;
    int c = (rgn & 1) * 24 + nb * 8 + gg;
    int k = (rgn >> 1) * 16 + 2 * tt + j * 8;
    W2A[rgn * 128 + lane * 4 + r] = packh2(w2g[c * 256 + k], w2g[c * 256 + k + 1]);
  }
  for (int f2 = tid; f2 < 2048; f2 += 512) {
    int r = f2 & 1, lane = (f2 >> 1) & 31, rgn = f2 >> 6;
    int gg = lane >> 2, tt = lane & 3;
    int c = (rgn & 1) * 24 + 16 + gg;
    int k = (rgn >> 1) * 16 + 2 * tt + r * 8;
    W2B[rgn * 64 + lane * 2 + r] = packh2(w2g[c * 256 + k], w2g[c * 256 + k + 1]);
  }

  uint32_t a1base[2];
  #pragma unroll
  for (int mc = 0; mc < 2; mc++)
    a1base[mc] = ph_u32 + (uint32_t)(((mh * 32 + mc * 16 + rowl) * PSH + koff) * 2);
  const uint32_t b1base = w1f_u32 + (uint32_t)(ns * 2 * 512 + lid * 16);
  // GEMM2 bases (full K): + ksg*32 (A), + ksg*1024 / ksg*512 (B)
  const uint32_t a2base  = hh_u32 + (uint32_t)(((mo * 16 + rowl) * HSH + koff) * 2);
  const uint32_t b2abase = w2a_u32 + (uint32_t)(nh * 512 + lid * 16);
  const uint32_t b2bbase = w2b_u32 + (uint32_t)(nh * 256 + lid * 8);

  const int niter = (NTILES + (int)gridDim.x - 1) / (int)gridDim.x;

  // ================= helpers =================
  auto issue_halo = [&](int tt2, int buf) {
    int bb = tt2 >> 10, y0 = ((tt2 >> 5) & 31) * 8, x0c = (tt2 & 31) * 8;
    const float* xb = xin + (size_t)bb * HWD * HWD * 48;
    uint32_t dbase = halo_u32 + (uint32_t)(buf * HALO_F * 4);
    for (int i = tid; i < 1200; i += 512) {
      int c4 = i % 12, pos = i / 12, row = pos / 10, col = pos % 10;
      int gy = y0 - 1 + row; gy = (gy < 0) ? -gy : ((gy >= HWD) ? 2 * HWD - 2 - gy : gy);
      int gx = x0c - 1 + col; gx = (gx < 0) ? -gx : ((gx >= HWD) ? 2 * HWD - 2 - gx : gx);
      CP_ASYNC16(dbase + (uint32_t)((row * HROW + col * 48 + c4 * 4) * 4),
                 xb + ((size_t)gy * HWD + gx) * 48 + c4 * 4);
    }
  };

  // build_tile: runs on threads 0..255 only (warps 0..7)
  auto build_tile = [&](int tt2, int buf, int fbuf) {
    const float* hs = sm + F_HALO + buf * HALO_F;
    // x-copy: P[pix][k<48]; 256 threads, 3 c4-groups each
    {
      int pix = tid >> 2, q = tid & 3;
      int py = pix >> 3, px = pix & 7;
      int base = (py + 1) * HROW + (px + 1) * 48;
      #pragma unroll
      for (int rep = 0; rep < 3; rep++) {
        int cc4 = q + rep * 4;
        const float4 v = *(const float4*)&hs[base + cc4 * 4];
        uint2 u; u.x = packh2(v.x, v.y); u.y = packh2(v.z, v.w);
        *(uint2*)&Ph[pix * PSH + cc4 * 4] = u;
      }
    }
    // depthwise convs: 192 merged tasks (threads 0..191)
    if (tid < 192) {
      int ch = tid % 48, pyb = (tid / 48) * 2;
      float v[4][10];
      #pragma unroll
      for (int dy = 0; dy < 4; dy++)
        #pragma unroll
        for (int qq = 0; qq < 10; qq++)
          v[dy][qq] = hs[(pyb + dy) * HROW + qq * 48 + ch];
      #pragma unroll
      for (int f = 0; f < 2; f++) {
        const float* cf = sfilt + (f * 48 + ch) * 9;
        float w[9];
        #pragma unroll
        for (int e = 0; e < 9; e++) w[e] = cf[e];
        int K = 48 + f * 48 + ch;
        #pragma unroll
        for (int p2 = 0; p2 < 2; p2++) {
          float acc[8] = {0.f,0.f,0.f,0.f,0.f,0.f,0.f,0.f};
          #pragma unroll
          for (int dy = 0; dy < 3; dy++)
            #pragma unroll
            for (int dx = 0; dx < 3; dx++) {
              float ww = w[dy * 3 + dx];
              #pragma unroll
              for (int i = 0; i < 8; i++)
                acc[i] = fmaf(v[p2 + dy][i + dx], ww, acc[i]);
            }
          #pragma unroll
          for (int i = 0; i < 8; i++)
            Ph[((pyb + p2) * 8 + i) * PSH + K] = __float2half_rn(acc[i]);
        }
      }
    } else {
      // fire mask (threads 192..255)
      int p = tid - 192;
      int bb = tt2 >> 10, y0 = ((tt2 >> 5) & 31) * 8, x0c = (tt2 & 31) * 8;
      int py = p >> 3, px = p & 7;
      uint32_t n = ((uint32_t)bb * HWD + (uint32_t)(y0 + py)) * HWD + (uint32_t)(x0c + px);
      uint32_t r0, r1;
      threefry2x32(key0, key1, 0u, n, r0, r1);
      float u = __uint_as_float(((r0 ^ r1) >> 9) | 0x3f800000u) - 1.0f;
      sfire[fbuf * 64 + p] = (u > 0.5f) ? 1.0f : 0.0f;
    }
  };

  // ================= prologue: tile0 =================
  {
    int tile0 = (int)blockIdx.x;
    if (tile0 < NTILES) issue_halo(tile0, 0);
    CP_COMMIT();
    CP_WAIT0();
    __syncthreads();             // halo(t0) + weights/filters visible
    if (tile0 < NTILES && tid < 256) build_tile(tile0, 0, 0);
  }
  int pb = 0, ff = 0;

  // ================= pipelined tile loop =================
  for (int iter = 0; iter < niter; iter++) {
    int tile = iter * (int)gridDim.x + (int)blockIdx.x;
    if (tile >= NTILES) break;
    int ntile = tile + (int)gridDim.x;

    const int bb = tile >> 10;
    const int y0 = ((tile >> 5) & 31) * 8;
    const int x0c = (tile & 31) * 8;

    // ---- interval A: Ph(tile)/fire ready; issue prefetch(n+1); GEMM1 ----
    __syncthreads();
    if (ntile < NTILES) issue_halo(ntile, pb ^ 1);
    CP_COMMIT();

    {
      float acc[2][4][4];
      #pragma unroll
      for (int mc = 0; mc < 2; mc++)
        #pragma unroll
        for (int nb = 0; nb < 4; nb++)
          #pragma unroll
          for (int e = 0; e < 4; e++) acc[mc][nb][e] = 0.f;

      #pragma unroll
      for (int ks = 0; ks < 9; ks++) {
        uint32_t b[4][2];
        LDS_V4(b[0][0], b[0][1], b[1][0], b[1][1], b1base + ks * 8192);
        LDS_V4(b[2][0], b[2][1], b[3][0], b[3][1], b1base + ks * 8192 + 512);
        #pragma unroll
        for (int mc = 0; mc < 2; mc++) {
          uint32_t a0, a1, a2, a3;
          LDMATRIX_X4(a0, a1, a2, a3, a1base[mc] + ks * 32);
          #pragma unroll
          for (int nb = 0; nb < 4; nb++)
            mma_f16(acc[mc][nb], a0, a1, a2, a3, b[nb][0], b[nb][1]);
        }
      }
      // epilogue1: bias + leaky -> H fp16
      #pragma unroll
      for (int mc = 0; mc < 2; mc++)
        #pragma unroll
        for (int nb = 0; nb < 4; nb++) {
          int row = mh * 32 + mc * 16 + g;
          int col = ns * 32 + nb * 8 + 2 * t;
          float b0 = sb1[col], b1v = sb1[col + 1];
          float v0 = acc[mc][nb][0] + b0;
          float v1 = acc[mc][nb][1] + b1v;
          v0 = (v0 > 0.f) ? v0 : 0.01f * v0;
          v1 = (v1 > 0.f) ? v1 : 0.01f * v1;
          *(__half2*)&Hh[row * HSH + col] = __floats2half2_rn(v0, v1);
          float v2 = acc[mc][nb][2] + b0;
          float v3 = acc[mc][nb][3] + b1v;
          v2 = (v2 > 0.f) ? v2 : 0.01f * v2;
          v3 = (v3 > 0.f) ? v3 : 0.01f * v3;
          *(__half2*)&Hh[(row + 8) * HSH + col] = __floats2half2_rn(v2, v3);
        }
    }

    // ---- interval B: warps 0-7 build(n+1); warps 8-15 GEMM2(n)+epilogue2 ----
    CP_WAIT0();
    __syncthreads();            // Hh visible + halo(n+1) visible; Ph free

    if (wid < 8) {
      if (ntile < NTILES) build_tile(ntile, pb ^ 1, ff ^ 1);
    } else {
      float acc2[3][4];
      #pragma unroll
      for (int nb = 0; nb < 3; nb++)
        #pragma unroll
        for (int e = 0; e < 4; e++) acc2[nb][e] = 0.f;

      #pragma unroll
      for (int ksg = 0; ksg < 16; ksg++) {
        uint32_t b2[3][2];
        LDS_V4(b2[0][0], b2[0][1], b2[1][0], b2[1][1], b2abase + ksg * 1024);
        LDS_V2(b2[2][0], b2[2][1], b2bbase + ksg * 512);
        uint32_t a0, a1, a2, a3;
        LDMATRIX_X4(a0, a1, a2, a3, a2base + ksg * 32);
        #pragma unroll
        for (int nb = 0; nb < 3; nb++)
          mma_f16(acc2[nb], a0, a1, a2, a3, b2[nb][0], b2[nb][1]);
      }

      // epilogue2 (full sums, no partials): fire + masked residual -> gmem
      const float* hs = sm + F_HALO + pb * HALO_F;
      #pragma unroll
      for (int nb = 0; nb < 3; nb++) {
        int c = nh * 24 + nb * 8 + 2 * t;
        #pragma unroll
        for (int hf = 0; hf < 2; hf++) {
          int pix = mo * 16 + g + hf * 8;
          int py = pix >> 3, px = pix & 7;
          float fire = sfire[ff * 64 + pix];
          float d0 = acc2[nb][hf * 2 + 0];
          float d1 = acc2[nb][hf * 2 + 1];
          int hb = (py + 1) * HROW + (px + 1) * 48;
          float xo0 = hs[hb + c];
          float xo1 = hs[hb + c + 1];
          float o0 = xo0 + ((c     >= 3) ? fire * d0 : 0.f);
          float o1 = xo1 + ((c + 1 >= 3) ? fire * d1 : 0.f);
          float* op = xout + (((size_t)bb * HWD + (y0 + py)) * HWD + (x0c + px)) * 48 + c;
          *(float2*)op = make_float2(o0, o1);
        }
      }
    }
    pb ^= 1; ff ^= 1;
    // loop-top sync (interval A) orders epilogue2/conv reads before next prefetch
  }
}

// ---------------- launcher ----------------
extern "C" void kernel_launch(void* const* d_in, const int* in_sizes, int n_in,
                              void* d_out, int out_size)
{
  const float* x     = (const float*)d_in[0];
  const float* filt0 = (const float*)d_in[1];
  const float* filt1 = (const float*)d_in[2];
  const float* w1    = (const float*)d_in[3];
  const float* b1    = (const float*)d_in[4];
  const float* w2    = (const float*)d_in[5];

  float* xbuf = nullptr;
  cudaGetSymbolAddress((void**)&xbuf, g_xbuf);
  float* outp = (float*)d_out;

  int nsm = 148;
  cudaDeviceGetAttribute(&nsm, cudaDevAttrMultiProcessorCount, 0);

  cudaFuncSetAttribute(nca_step_mma, cudaFuncAttributeMaxDynamicSharedMemorySize,
                       (int)SMEM_BYTES);

  const float* src = x;
  for (int i = 0; i < 4; i++) {
    uint32_t f0, f1; threefry2x32(0u, 42u, 0u, (uint32_t)i, f0, f1);
    uint32_t a0, a1; threefry2x32(f0, f1, 0u, 0u, a0, a1);
    float* dst = (i & 1) ? outp : xbuf;
    if (i == 3) dst = outp;
    nca_step_mma<<<nsm, 512, SMEM_BYTES>>>(src, dst, filt0, filt1, b1, w1, w2,
                                           a0, a1);
    src = dst;
  }
}